// round 5
// baseline (speedup 1.0000x reference)
#include <cuda_runtime.h>
#include <cstdint>

#define N_NODES 50000
#define N_REL 8
#define N_EDGE 64000
#define D 128
#define TILES_PER_REL (N_EDGE / 128)   // 500
#define EDGE_CTAS 18                   // per relation -> 144 persistent CTAs

// ---------------- common helpers ----------------
__device__ __forceinline__ uint32_t f2tf32(float f) {
    uint32_t r;
    asm("cvt.rna.tf32.f32 %0, %1;" : "=r"(r) : "f"(f));
    return r;
}
__device__ __forceinline__ void cp16(uint32_t sa, const float* g) {
    asm volatile("cp.async.cg.shared.global [%0], [%1], 16;" ::"r"(sa), "l"(g));
}
__device__ __forceinline__ void cp_commit() { asm volatile("cp.async.commit_group;"); }
template <int N>
__device__ __forceinline__ void cp_wait() { asm volatile("cp.async.wait_group %0;" ::"n"(N)); }

__device__ __forceinline__ void mma_tf32(float c[4], const uint32_t a[4], const uint32_t b[2]) {
    asm volatile(
        "mma.sync.aligned.m16n8k8.row.col.f32.tf32.tf32.f32 "
        "{%0,%1,%2,%3}, {%4,%5,%6,%7}, {%8,%9}, {%0,%1,%2,%3};\n"
        : "+f"(c[0]), "+f"(c[1]), "+f"(c[2]), "+f"(c[3])
        : "r"(a[0]), "r"(a[1]), "r"(a[2]), "r"(a[3]), "r"(b[0]), "r"(b[1]));
}

// Pre-rounded (RNA tf32) relation weights, plain [r][k][n] layout.
__device__ float g_wt[N_REL * D * D];

extern "C" __global__ void pack_w_kernel(const float* __restrict__ weight) {
    int r = blockIdx.x;
    for (int i = threadIdx.x; i < D * D; i += blockDim.x)
        g_wt[r * D * D + i] = __uint_as_float(f2tf32(weight[r * D * D + i]));
}

// ---------------------------------------------------------------------------
// Edge kernel: persistent per-relation CTAs, B resident in smem, whole-tile A
// double buffered (XOR-swizzled, stride 128), raw-fp32 fragments (HW tf32
// truncation), C staged into the consumed A buffer, red.v4 scatter.
// smem: Bs[128*136] | A0[128*128] | A1[128*128]  = 200704 B
// ---------------------------------------------------------------------------
#define BS_FLOATS (128 * 136)
#define ABUF_FLOATS (128 * 128)
#define EDGE_SMEM_BYTES ((BS_FLOATS + 2 * ABUF_FLOATS) * 4)

extern "C" __global__ void __launch_bounds__(256)
edge_kernel(const float* __restrict__ x, const int* __restrict__ src,
            const int* __restrict__ dst, const float* __restrict__ ew,
            float* __restrict__ out) {
    extern __shared__ float smem[];
    float* Bs = smem;
    float* Abuf[2] = {smem + BS_FLOATS, smem + BS_FLOATS + ABUF_FLOATS};

    const int tid = threadIdx.x;
    const int warp = tid >> 5, lane = tid & 31;
    const int r = blockIdx.y;
    const int s0 = (blockIdx.x * TILES_PER_REL) / EDGE_CTAS;
    const int e1 = ((blockIdx.x + 1) * TILES_PER_REL) / EDGE_CTAS;
    const int T = e1 - s0;
    const int ebase = r * N_EDGE + s0 * 128;

    const uint32_t bs_base = (uint32_t)__cvta_generic_to_shared(Bs);
    const uint32_t a_base[2] = {(uint32_t)__cvta_generic_to_shared(Abuf[0]),
                                (uint32_t)__cvta_generic_to_shared(Abuf[1])};

    // gather one A tile (128 edges x 128 feats) into swizzled buffer
    auto issueA = [&](int i, int buf) {
        const int eb = ebase + i * 128;
        const uint32_t ab = a_base[buf];
#pragma unroll
        for (int it = 0; it < 16; it++) {
            int row = warp + it * 8;                       // warp-uniform
            int srow = __ldg(&src[eb + row]);
            cp16(ab + (uint32_t)row * 512 + (uint32_t)((lane ^ warp) << 4),
                 x + (size_t)srow * D + lane * 4);
        }
    };

    // B (resident, padded stride 136) + A(0), one cp.async group
    {
        const float* Wr = g_wt + (size_t)r * D * D;
#pragma unroll
        for (int it = 0; it < 16; it++) {
            int j = tid + it * 256;
            int k = j >> 5, q = j & 31;
            cp16(bs_base + (uint32_t)(k * 136 + q * 4) * 4, Wr + j * 4);
        }
        issueA(0, 0);
        cp_commit();
    }

    const int g = lane >> 2, tg = lane & 3;
    const int mw = warp >> 1, nw = warp & 1;

    for (int i = 0; i < T; i++) {
        const int b = i & 1;
        __syncthreads();  // scatter of tile i-1 (from buf b^1) fully read

        if (i + 1 < T) { issueA(i + 1, b ^ 1); cp_commit(); cp_wait<1>(); }
        else cp_wait<0>();
        __syncthreads();  // A(i) (and B on first iter) visible

        float acc[2][8][4];
#pragma unroll
        for (int mi = 0; mi < 2; mi++)
#pragma unroll
            for (int j = 0; j < 8; j++)
#pragma unroll
                for (int c4 = 0; c4 < 4; c4++) acc[mi][j][c4] = 0.f;

        const float* As = Abuf[b];
#pragma unroll
        for (int k0 = 0; k0 < 128; k0 += 8) {
            uint32_t a[2][4];
#pragma unroll
            for (int mi = 0; mi < 2; mi++) {
                const float* Ar = As + (mw * 32 + mi * 16 + g) * 128;
                int c0 = (((k0 >> 2)) ^ g) * 4 + tg;
                int c1 = (((k0 >> 2) + 1) ^ g) * 4 + tg;
                a[mi][0] = __float_as_uint(Ar[c0]);
                a[mi][1] = __float_as_uint(Ar[8 * 128 + c0]);
                a[mi][2] = __float_as_uint(Ar[c1]);
                a[mi][3] = __float_as_uint(Ar[8 * 128 + c1]);
            }
            uint32_t bf[8][2];
#pragma unroll
            for (int j = 0; j < 8; j++) {
                int col = nw * 64 + 8 * j + g;
                bf[j][0] = __float_as_uint(Bs[(k0 + tg) * 136 + col]);
                bf[j][1] = __float_as_uint(Bs[(k0 + tg + 4) * 136 + col]);
            }
#pragma unroll
            for (int mi = 0; mi < 2; mi++)
#pragma unroll
                for (int j = 0; j < 8; j++)
                    mma_tf32(acc[mi][j], a[mi], bf[j]);
        }
        __syncthreads();  // all warps done reading A(i)

        // stage C*ew into Abuf[b] (same XOR granule swizzle)
        float* Cs = Abuf[b];
        const int eb = ebase + i * 128;
#pragma unroll
        for (int mi = 0; mi < 2; mi++) {
            int row0 = mw * 32 + mi * 16 + g;  // row0 & 7 == g
            float w0 = __ldg(&ew[eb + row0]);
            float w1 = __ldg(&ew[eb + row0 + 8]);
#pragma unroll
            for (int j = 0; j < 8; j++) {
                int col = nw * 64 + 8 * j + 2 * tg;
                int fi = row0 * 128 + (((col >> 2) ^ g) << 2) + (col & 3);
                *(float2*)&Cs[fi] = make_float2(acc[mi][j][0] * w0, acc[mi][j][1] * w0);
                *(float2*)&Cs[fi + 8 * 128] = make_float2(acc[mi][j][2] * w1, acc[mi][j][3] * w1);
            }
        }
        __syncthreads();

        // 128-bit atomic scatter (fire-and-forget, overlaps next tile's MMAs)
#pragma unroll
        for (int it = 0; it < 16; it++) {
            int row = warp + it * 8;                       // warp-uniform
            int d = __ldg(&dst[eb + row]);
            const float4 v = *(const float4*)&Cs[row * 128 + ((lane ^ warp) << 2)];
            float* p = out + (size_t)d * D + lane * 4;
            asm volatile("red.global.add.v4.f32 [%0], {%1,%2,%3,%4};"
                         ::"l"(p), "f"(v.x), "f"(v.y), "f"(v.z), "f"(v.w)
                         : "memory");
        }
    }
}

// ---------------------------------------------------------------------------
// Root kernel: unchanged round-2 structure (known good, RNA cvts kept)
// ---------------------------------------------------------------------------
#define CK 32
#define NCHUNK 4
#define ASTRIDE 36
#define BSTRIDE 136
#define AS_CHUNK (128 * ASTRIDE)
#define BS_CHUNK (CK * BSTRIDE)
#define GEMM_FLOATS (2 * AS_CHUNK + 2 * BS_CHUNK)
#define ROOT_SMEM (GEMM_FLOATS * 4)

__device__ __forceinline__ void compute_chunk(const float* __restrict__ As,
                                              const float* __restrict__ Bs,
                                              int g, int tg, int mw, int nw,
                                              float acc[2][8][4]) {
#pragma unroll
    for (int k0 = 0; k0 < CK; k0 += 8) {
        uint32_t a[2][4];
#pragma unroll
        for (int mi = 0; mi < 2; mi++) {
            const float* Ab = As + (mw * 32 + mi * 16 + g) * ASTRIDE + k0;
            a[mi][0] = f2tf32(Ab[tg]);
            a[mi][1] = f2tf32(Ab[8 * ASTRIDE + tg]);
            a[mi][2] = f2tf32(Ab[tg + 4]);
            a[mi][3] = f2tf32(Ab[8 * ASTRIDE + tg + 4]);
        }
        uint32_t b[8][2];
#pragma unroll
        for (int j = 0; j < 8; j++) {
            int col = nw * 64 + 8 * j + g;
            b[j][0] = f2tf32(Bs[(k0 + tg) * BSTRIDE + col]);
            b[j][1] = f2tf32(Bs[(k0 + tg + 4) * BSTRIDE + col]);
        }
#pragma unroll
        for (int mi = 0; mi < 2; mi++)
#pragma unroll
            for (int j = 0; j < 8; j++)
                mma_tf32(acc[mi][j], a[mi], b[j]);
    }
}

extern "C" __global__ void __launch_bounds__(256, 2)
root_kernel(const float* __restrict__ x, const float* __restrict__ root_w,
            const float* __restrict__ root_b, const float* __restrict__ bias,
            float* __restrict__ out) {
    extern __shared__ float smem[];
    float* Asb[2] = {smem, smem + AS_CHUNK};
    float* Bsb[2] = {smem + 2 * AS_CHUNK, smem + 2 * AS_CHUNK + BS_CHUNK};

    const int tid = threadIdx.x;
    const int n0 = blockIdx.x * 128;

    auto issue = [&](int c, int buf) {
        int k0 = c * CK;
        uint32_t as_base = (uint32_t)__cvta_generic_to_shared(Asb[buf]);
        uint32_t bs_base = (uint32_t)__cvta_generic_to_shared(Bsb[buf]);
#pragma unroll
        for (int it = 0; it < 4; it++) {
            int s = tid + it * 256;
            int row = s >> 3, off = (s & 7) * 4;
            int gr = n0 + row;
            if (gr >= N_NODES) gr = 0;
            cp16(as_base + (row * ASTRIDE + off) * 4, x + (size_t)gr * D + k0 + off);
        }
#pragma unroll
        for (int it = 0; it < 4; it++) {
            int s = tid + it * 256;
            int k = s >> 5, off = (s & 31) * 4;
            cp16(bs_base + (k * BSTRIDE + off) * 4, root_w + (size_t)(k0 + k) * D + off);
        }
        cp_commit();
    };

    const int lane = tid & 31, warp = tid >> 5;
    const int g = lane >> 2, tg = lane & 3;
    const int mw = warp >> 1, nw = warp & 1;

    float acc[2][8][4];
#pragma unroll
    for (int mi = 0; mi < 2; mi++)
#pragma unroll
        for (int j = 0; j < 8; j++)
#pragma unroll
            for (int c4 = 0; c4 < 4; c4++) acc[mi][j][c4] = 0.f;

    issue(0, 0);
#pragma unroll
    for (int c = 0; c < NCHUNK; c++) {
        if (c + 1 < NCHUNK) { issue(c + 1, (c + 1) & 1); cp_wait<1>(); }
        else cp_wait<0>();
        __syncthreads();
        compute_chunk(Asb[c & 1], Bsb[c & 1], g, tg, mw, nw, acc);
        __syncthreads();
    }

#pragma unroll
    for (int mi = 0; mi < 2; mi++) {
        int row0 = n0 + mw * 32 + mi * 16 + g;
#pragma unroll
        for (int j = 0; j < 8; j++) {
            int col = nw * 64 + 8 * j + 2 * tg;
            float b0 = root_b[col] + bias[col];
            float b1 = root_b[col + 1] + bias[col + 1];
            if (row0 < N_NODES)
                *(float2*)&out[(size_t)row0 * D + col] =
                    make_float2(acc[mi][j][0] + b0, acc[mi][j][1] + b1);
            if (row0 + 8 < N_NODES)
                *(float2*)&out[(size_t)(row0 + 8) * D + col] =
                    make_float2(acc[mi][j][2] + b0, acc[mi][j][3] + b1);
        }
    }
}

// ---------------------------------------------------------------------------
// ReLU
// ---------------------------------------------------------------------------
extern "C" __global__ void relu_kernel(float4* __restrict__ out, int n4) {
    int i = blockIdx.x * blockDim.x + threadIdx.x;
    int stride = gridDim.x * blockDim.x;
    for (; i < n4; i += stride) {
        float4 v = out[i];
        v.x = fmaxf(v.x, 0.f);
        v.y = fmaxf(v.y, 0.f);
        v.z = fmaxf(v.z, 0.f);
        v.w = fmaxf(v.w, 0.f);
        out[i] = v;
    }
}

extern "C" void kernel_launch(void* const* d_in, const int* in_sizes, int n_in,
                              void* d_out, int out_size) {
    const float* x      = (const float*)d_in[0];
    const int*   src    = (const int*)d_in[1];
    const int*   dst    = (const int*)d_in[2];
    const float* ew     = (const float*)d_in[3];
    const float* weight = (const float*)d_in[4];
    const float* root_w = (const float*)d_in[5];
    const float* root_b = (const float*)d_in[6];
    const float* bias   = (const float*)d_in[7];
    float* out = (float*)d_out;

    cudaFuncSetAttribute(root_kernel, cudaFuncAttributeMaxDynamicSharedMemorySize, ROOT_SMEM);
    cudaFuncSetAttribute(edge_kernel, cudaFuncAttributeMaxDynamicSharedMemorySize, EDGE_SMEM_BYTES);

    pack_w_kernel<<<N_REL, 256>>>(weight);

    int root_blocks = (N_NODES + 127) / 128;  // 391
    root_kernel<<<root_blocks, 256, ROOT_SMEM>>>(x, root_w, root_b, bias, out);

    dim3 egrid(EDGE_CTAS, N_REL);  // 18 x 8 = 144 persistent CTAs
    edge_kernel<<<egrid, 256, EDGE_SMEM_BYTES>>>(x, src, dst, ew, out);

    int n4 = out_size / 4;
    relu_kernel<<<592, 256>>>((float4*)out, n4);
}

// round 6
// speedup vs baseline: 1.2153x; 1.2153x over previous
#include <cuda_runtime.h>
#include <cstdint>

#define N_NODES 50000
#define N_REL 8
#define N_EDGE 64000
#define D 128

// K-chunked pipelined tile: M=128, N=128, K in 4 chunks of 32, double buffered.
#define CK 32
#define NCHUNK 4
#define ASTRIDE 36     // 36 mod 32 = 4 -> conflict-free A-fragment LDS (4g+tg)
#define BSTRIDE 136    // 136 mod 32 = 8 -> conflict-free B-fragment LDS (8tg+g)
#define AS_CHUNK (128 * ASTRIDE)   // 4608 floats per buffer
#define BS_CHUNK (CK * BSTRIDE)    // 4352 floats per buffer
#define CS_STRIDE 132              // C staging stride for scatter

#define GEMM_FLOATS (2 * AS_CHUNK + 2 * BS_CHUNK)   // 17920 floats = 71680 B
#define EDGE_SMEM ((GEMM_FLOATS + 384) * 4)          // + src/dst/ew
#define ROOT_SMEM (GEMM_FLOATS * 4)

__device__ __forceinline__ uint32_t f2tf32(float f) {
    uint32_t r;
    asm("cvt.rna.tf32.f32 %0, %1;" : "=r"(r) : "f"(f));
    return r;
}
__device__ __forceinline__ void cp16(uint32_t sa, const float* g) {
    asm volatile("cp.async.cg.shared.global [%0], [%1], 16;" ::"r"(sa), "l"(g));
}
__device__ __forceinline__ void cp_commit() { asm volatile("cp.async.commit_group;"); }
template <int N>
__device__ __forceinline__ void cp_wait() { asm volatile("cp.async.wait_group %0;" ::"n"(N)); }

__device__ __forceinline__ void mma_tf32(float c[4], const uint32_t a[4], const uint32_t b[2]) {
    asm volatile(
        "mma.sync.aligned.m16n8k8.row.col.f32.tf32.tf32.f32 "
        "{%0,%1,%2,%3}, {%4,%5,%6,%7}, {%8,%9}, {%0,%1,%2,%3};\n"
        : "+f"(c[0]), "+f"(c[1]), "+f"(c[2]), "+f"(c[3])
        : "r"(a[0]), "r"(a[1]), "r"(a[2]), "r"(a[3]), "r"(b[0]), "r"(b[1]));
}

// Pre-rounded (RNA tf32) weights: relations + root. Plain [k][n] layouts.
__device__ float g_wt[N_REL * D * D];
__device__ float g_rw[D * D];

extern "C" __global__ void pack_w_kernel(const float* __restrict__ weight,
                                         const float* __restrict__ root_w) {
    int r = blockIdx.x;
    if (r < N_REL) {
        for (int i = threadIdx.x; i < D * D; i += blockDim.x)
            g_wt[r * D * D + i] = __uint_as_float(f2tf32(weight[r * D * D + i]));
    } else {
        for (int i = threadIdx.x; i < D * D; i += blockDim.x)
            g_rw[i] = __uint_as_float(f2tf32(root_w[i]));
    }
}

// Cvt-free mainloop: raw fp32 A bits (HW tf32 truncation), pre-rounded B.
__device__ __forceinline__ void compute_chunk(const float* __restrict__ As,
                                              const float* __restrict__ Bs,
                                              int g, int tg, int mw, int nw,
                                              float acc[2][8][4]) {
#pragma unroll
    for (int k0 = 0; k0 < CK; k0 += 8) {
        uint32_t a[2][4];
#pragma unroll
        for (int mi = 0; mi < 2; mi++) {
            const float* Ab = As + (mw * 32 + mi * 16 + g) * ASTRIDE + k0;
            a[mi][0] = __float_as_uint(Ab[tg]);
            a[mi][1] = __float_as_uint(Ab[8 * ASTRIDE + tg]);
            a[mi][2] = __float_as_uint(Ab[tg + 4]);
            a[mi][3] = __float_as_uint(Ab[8 * ASTRIDE + tg + 4]);
        }
        uint32_t b[8][2];
#pragma unroll
        for (int j = 0; j < 8; j++) {
            int col = nw * 64 + 8 * j + g;
            b[j][0] = __float_as_uint(Bs[(k0 + tg) * BSTRIDE + col]);
            b[j][1] = __float_as_uint(Bs[(k0 + tg + 4) * BSTRIDE + col]);
        }
#pragma unroll
        for (int mi = 0; mi < 2; mi++)
#pragma unroll
            for (int j = 0; j < 8; j++)
                mma_tf32(acc[mi][j], a[mi], b[j]);
    }
}

// ---------------------------------------------------------------------------
// Kernel 1: out = x @ root_w + root_b + bias (dense init of all rows)
// ---------------------------------------------------------------------------
extern "C" __global__ void __launch_bounds__(256, 2)
root_kernel(const float* __restrict__ x, const float* __restrict__ root_b,
            const float* __restrict__ bias, float* __restrict__ out) {
    extern __shared__ float smem[];
    float* Asb[2] = {smem, smem + AS_CHUNK};
    float* Bsb[2] = {smem + 2 * AS_CHUNK, smem + 2 * AS_CHUNK + BS_CHUNK};

    const int tid = threadIdx.x;
    const int n0 = blockIdx.x * 128;

    auto issue = [&](int c, int buf) {
        int k0 = c * CK;
        uint32_t as_base = (uint32_t)__cvta_generic_to_shared(Asb[buf]);
        uint32_t bs_base = (uint32_t)__cvta_generic_to_shared(Bsb[buf]);
#pragma unroll
        for (int it = 0; it < 4; it++) {
            int s = tid + it * 256;
            int row = s >> 3, off = (s & 7) * 4;
            int gr = n0 + row;
            if (gr >= N_NODES) gr = 0;
            cp16(as_base + (row * ASTRIDE + off) * 4, x + (size_t)gr * D + k0 + off);
        }
#pragma unroll
        for (int it = 0; it < 4; it++) {
            int s = tid + it * 256;
            int k = s >> 5, off = (s & 31) * 4;
            cp16(bs_base + (k * BSTRIDE + off) * 4, g_rw + (size_t)(k0 + k) * D + off);
        }
        cp_commit();
    };

    const int lane = tid & 31, warp = tid >> 5;
    const int g = lane >> 2, tg = lane & 3;
    const int mw = warp >> 1, nw = warp & 1;

    float acc[2][8][4];
#pragma unroll
    for (int mi = 0; mi < 2; mi++)
#pragma unroll
        for (int j = 0; j < 8; j++)
#pragma unroll
            for (int c4 = 0; c4 < 4; c4++) acc[mi][j][c4] = 0.f;

    issue(0, 0);
#pragma unroll
    for (int c = 0; c < NCHUNK; c++) {
        if (c + 1 < NCHUNK) { issue(c + 1, (c + 1) & 1); cp_wait<1>(); }
        else cp_wait<0>();
        __syncthreads();
        compute_chunk(Asb[c & 1], Bsb[c & 1], g, tg, mw, nw, acc);
        __syncthreads();
    }

#pragma unroll
    for (int mi = 0; mi < 2; mi++) {
        int row0 = n0 + mw * 32 + mi * 16 + g;
#pragma unroll
        for (int j = 0; j < 8; j++) {
            int col = nw * 64 + 8 * j + 2 * tg;
            float b0 = root_b[col] + bias[col];
            float b1 = root_b[col + 1] + bias[col + 1];
            if (row0 < N_NODES)
                *(float2*)&out[(size_t)row0 * D + col] =
                    make_float2(acc[mi][j][0] + b0, acc[mi][j][1] + b1);
            if (row0 + 8 < N_NODES)
                *(float2*)&out[(size_t)(row0 + 8) * D + col] =
                    make_float2(acc[mi][j][2] + b0, acc[mi][j][3] + b1);
        }
    }
}

// ---------------------------------------------------------------------------
// Kernel 2: per-relation edge tiles: gather x[src] -> GEMM W_r -> *ew ->
//           red.v4 atomic scatter into out[dst]
// ---------------------------------------------------------------------------
extern "C" __global__ void __launch_bounds__(256, 2)
edge_kernel(const float* __restrict__ x, const int* __restrict__ src,
            const int* __restrict__ dst, const float* __restrict__ ew,
            float* __restrict__ out) {
    extern __shared__ float smem[];
    float* Asb[2] = {smem, smem + AS_CHUNK};
    float* Bsb[2] = {smem + 2 * AS_CHUNK, smem + 2 * AS_CHUNK + BS_CHUNK};
    int* s_src = (int*)(smem + GEMM_FLOATS);
    int* s_dst = s_src + 128;
    float* s_ew = (float*)(s_dst + 128);

    const int tid = threadIdx.x;
    const int r = blockIdx.y;
    const int e0 = blockIdx.x * 128;
    const int ebase = r * N_EDGE + e0;
    const float* W = g_wt + (size_t)r * D * D;

    if (tid < 128) {
        s_src[tid] = src[ebase + tid];
        s_dst[tid] = dst[ebase + tid];
        s_ew[tid] = ew[ebase + tid];
    }
    __syncthreads();

    auto issue = [&](int c, int buf) {
        int k0 = c * CK;
        uint32_t as_base = (uint32_t)__cvta_generic_to_shared(Asb[buf]);
        uint32_t bs_base = (uint32_t)__cvta_generic_to_shared(Bsb[buf]);
#pragma unroll
        for (int it = 0; it < 4; it++) {
            int s = tid + it * 256;
            int row = s >> 3, off = (s & 7) * 4;
            cp16(as_base + (row * ASTRIDE + off) * 4,
                 x + (size_t)s_src[row] * D + k0 + off);
        }
#pragma unroll
        for (int it = 0; it < 4; it++) {
            int s = tid + it * 256;
            int k = s >> 5, off = (s & 31) * 4;
            cp16(bs_base + (k * BSTRIDE + off) * 4, W + (size_t)(k0 + k) * D + off);
        }
        cp_commit();
    };

    const int lane = tid & 31, warp = tid >> 5;
    const int g = lane >> 2, tg = lane & 3;
    const int mw = warp >> 1, nw = warp & 1;

    float acc[2][8][4];
#pragma unroll
    for (int mi = 0; mi < 2; mi++)
#pragma unroll
        for (int j = 0; j < 8; j++)
#pragma unroll
            for (int c4 = 0; c4 < 4; c4++) acc[mi][j][c4] = 0.f;

    issue(0, 0);
#pragma unroll
    for (int c = 0; c < NCHUNK; c++) {
        if (c + 1 < NCHUNK) { issue(c + 1, (c + 1) & 1); cp_wait<1>(); }
        else cp_wait<0>();
        __syncthreads();
        compute_chunk(Asb[c & 1], Bsb[c & 1], g, tg, mw, nw, acc);
        __syncthreads();
    }

    // stage scaled C into smem (overlay pipeline buffers) for 128-bit REDs
    float* Cs = smem;  // 128 * CS_STRIDE = 16896 floats < GEMM_FLOATS; idx arrays safe
#pragma unroll
    for (int mi = 0; mi < 2; mi++) {
        int row0 = mw * 32 + mi * 16 + g;
        float w0 = s_ew[row0], w1 = s_ew[row0 + 8];
#pragma unroll
        for (int j = 0; j < 8; j++) {
            int col = nw * 64 + 8 * j + 2 * tg;
            *(float2*)&Cs[row0 * CS_STRIDE + col] =
                make_float2(acc[mi][j][0] * w0, acc[mi][j][1] * w0);
            *(float2*)&Cs[(row0 + 8) * CS_STRIDE + col] =
                make_float2(acc[mi][j][2] * w1, acc[mi][j][3] * w1);
        }
    }
    __syncthreads();

#pragma unroll
    for (int it = 0; it < 16; it++) {
        int t = tid + it * 256;
        int row = t >> 5, q = t & 31;
        const float4 v = *(const float4*)&Cs[row * CS_STRIDE + q * 4];
        float* p = out + (size_t)s_dst[row] * D + q * 4;
        asm volatile("red.global.add.v4.f32 [%0], {%1,%2,%3,%4};"
                     ::"l"(p), "f"(v.x), "f"(v.y), "f"(v.z), "f"(v.w)
                     : "memory");
    }
}

// ---------------------------------------------------------------------------
// Kernel 3: in-place ReLU
// ---------------------------------------------------------------------------
extern "C" __global__ void relu_kernel(float4* __restrict__ out, int n4) {
    int i = blockIdx.x * blockDim.x + threadIdx.x;
    int stride = gridDim.x * blockDim.x;
    for (; i < n4; i += stride) {
        float4 v = out[i];
        v.x = fmaxf(v.x, 0.f);
        v.y = fmaxf(v.y, 0.f);
        v.z = fmaxf(v.z, 0.f);
        v.w = fmaxf(v.w, 0.f);
        out[i] = v;
    }
}

extern "C" void kernel_launch(void* const* d_in, const int* in_sizes, int n_in,
                              void* d_out, int out_size) {
    const float* x      = (const float*)d_in[0];
    const int*   src    = (const int*)d_in[1];
    const int*   dst    = (const int*)d_in[2];
    const float* ew     = (const float*)d_in[3];
    const float* weight = (const float*)d_in[4];
    const float* root_w = (const float*)d_in[5];
    const float* root_b = (const float*)d_in[6];
    const float* bias   = (const float*)d_in[7];
    float* out = (float*)d_out;

    cudaFuncSetAttribute(root_kernel, cudaFuncAttributeMaxDynamicSharedMemorySize, ROOT_SMEM);
    cudaFuncSetAttribute(edge_kernel, cudaFuncAttributeMaxDynamicSharedMemorySize, EDGE_SMEM);

    pack_w_kernel<<<N_REL + 1, 256>>>(weight, root_w);

    int root_blocks = (N_NODES + 127) / 128;  // 391
    root_kernel<<<root_blocks, 256, ROOT_SMEM>>>(x, root_b, bias, out);

    dim3 egrid(N_EDGE / 128, N_REL);  // 500 x 8
    edge_kernel<<<egrid, 256, EDGE_SMEM>>>(x, src, dst, ew, out);

    int n4 = out_size / 4;
    relu_kernel<<<1184, 256>>>((float4*)out, n4);
}